// round 5
// baseline (speedup 1.0000x reference)
#include <cuda_runtime.h>
#include <cuda_fp16.h>
#include <cstdint>
#include <cstddef>

#define NNODES 16384
#define FDIM   768
#define DEG    4

// ---------------- scratch (device globals; no allocation allowed) ----------
__device__ float  g_P1[FDIM * 8];
__device__ float  g_P2[FDIM * 2];
__device__ __half g_W1ph[(size_t)4 * FDIM * FDIM];    // [3072,768] B GEMM1 (x0.25, fp16)
__device__ __half g_W2rh[(size_t)FDIM * FDIM];        // [768,768]  B GEMM2 (fp16)
__device__ float  g_e1[(size_t)NNODES * 8];
__device__ float  g_e2[(size_t)NNODES * 2];
__device__ __half g_agg1h[(size_t)NNODES * 4 * FDIM]; // [N,3072] A GEMM1 (fp16)
__device__ __half g_agg2h[(size_t)NNODES * FDIM];     // [N,768]  A GEMM2 (fp16)
__device__ float  g_pre[(size_t)NNODES * FDIM];
__device__ __half g_x1h[(size_t)NNODES * FDIM];       // layer-1 output (fp16)
__device__ int    g_is64;

// ---------------- helpers ---------------------------------------------------
__device__ __forceinline__ uint32_t smem_u32(const void* p) {
    uint32_t a;
    asm("{ .reg .u64 t; cvta.to.shared.u64 t, %1; cvt.u32.u64 %0, t; }" : "=r"(a) : "l"(p));
    return a;
}

__device__ __forceinline__ void cp16(uint32_t s, const void* g) {
    asm volatile("cp.async.cg.shared.global [%0], [%1], 16;" :: "r"(s), "l"(g));
}

__device__ __forceinline__ void ldsm_x4(uint32_t* r, uint32_t addr) {
    asm volatile("ldmatrix.sync.aligned.m8n8.x4.shared.b16 {%0,%1,%2,%3}, [%4];"
                 : "=r"(r[0]), "=r"(r[1]), "=r"(r[2]), "=r"(r[3]) : "r"(addr));
}

__device__ __forceinline__ void ldsm_x4_t(uint32_t* r, uint32_t addr) {
    asm volatile("ldmatrix.sync.aligned.m8n8.x4.trans.shared.b16 {%0,%1,%2,%3}, [%4];"
                 : "=r"(r[0]), "=r"(r[1]), "=r"(r[2]), "=r"(r[3]) : "r"(addr));
}

__device__ __forceinline__ void mma_f16(float* d, const uint32_t* a, const uint32_t* b) {
    asm volatile(
        "mma.sync.aligned.m16n8k16.row.col.f32.f16.f16.f32 "
        "{%0,%1,%2,%3}, {%4,%5,%6,%7}, {%8,%9}, {%0,%1,%2,%3};"
        : "+f"(d[0]), "+f"(d[1]), "+f"(d[2]), "+f"(d[3])
        : "r"(a[0]), "r"(a[1]), "r"(a[2]), "r"(a[3]), "r"(b[0]), "r"(b[1]));
}

__device__ __forceinline__ float block_reduce_256(float v, float* red) {
#pragma unroll
    for (int o = 16; o; o >>= 1) v += __shfl_down_sync(0xffffffffu, v, o);
    if ((threadIdx.x & 31) == 0) red[threadIdx.x >> 5] = v;
    __syncthreads();
    float r = 0.f;
    if (threadIdx.x < 8) r = red[threadIdx.x];
    if (threadIdx.x < 32) {
#pragma unroll
        for (int o = 4; o; o >>= 1) r += __shfl_down_sync(0xffu, r, o);
    }
    return r;
}

// ---------------- edge dtype probe ------------------------------------------
__global__ void detect_kernel(const unsigned long long* __restrict__ p) {
    __shared__ int bad;
    if (threadIdx.x == 0) bad = 0;
    __syncthreads();
    for (int i = threadIdx.x; i < 1024; i += blockDim.x)
        if (p[i] > 0xFFFFFFFFull) bad = 1;
    __syncthreads();
    if (threadIdx.x == 0) g_is64 = bad ? 0 : 1;
}

// ---------------- attention projection vectors P = W_h @ a_h ----------------
__global__ void __launch_bounds__(256) build_p(
    const float* __restrict__ W1, const float* __restrict__ a1s, const float* __restrict__ a1d,
    const float* __restrict__ W2, const float* __restrict__ a2s, const float* __restrict__ a2d)
{
    __shared__ float red[8];
    int k = blockIdx.x, j = blockIdx.y;
    const float *w, *a;
    if (j < 8) {
        int h = j & 3;
        w = W1 + (size_t)k * (4 * FDIM) + h * FDIM;
        a = (j < 4 ? a1s : a1d) + h * FDIM;
    } else {
        w = W2 + (size_t)k * FDIM;
        a = (j == 8) ? a2s : a2d;
    }
    float s = 0.f;
    for (int d = threadIdx.x; d < FDIM; d += 256) s += w[d] * a[d];
    float tot = block_reduce_256(s, red);
    if (threadIdx.x == 0) {
        if (j < 8) g_P1[k * 8 + j] = tot;
        else       g_P2[k * 2 + (j - 8)] = tot;
    }
}

// ---------------- merged W prep: W1 repack (x0.25) + W2 to fp16 --------------
__global__ void __launch_bounds__(256) build_w(const float* __restrict__ W1,
                                               const float* __restrict__ W2)
{
    const size_t S1 = (size_t)4 * FDIM * FDIM;
    const size_t S2 = (size_t)FDIM * FDIM;
    size_t idx = (size_t)blockIdx.x * 256 + threadIdx.x;
    if (idx < S1) {
        int j = (int)(idx % FDIM);
        int r = (int)(idx / FDIM);     // h*768 + k
        int h = r / FDIM, k = r % FDIM;
        g_W1ph[idx] = __float2half(0.25f * W1[(size_t)k * (4 * FDIM) + h * FDIM + j]);
    } else if (idx < S1 + S2) {
        size_t i2 = idx - S1;
        g_W2rh[i2] = __float2half(W2[i2]);
    }
}

// ---------------- per-node logits e = x @ P ----------------------------------
template <int NJ, typename T>
__global__ void __launch_bounds__(256) compute_e(
    const T* __restrict__ x, const float* __restrict__ P, float* __restrict__ e)
{
    __shared__ float sP[FDIM * NJ];
    for (int i = threadIdx.x; i < FDIM * NJ; i += 256) sP[i] = P[i];
    __syncthreads();
    int warp = threadIdx.x >> 5, lane = threadIdx.x & 31;
    for (int n = blockIdx.x * 8 + warp; n < NNODES; n += gridDim.x * 8) {
        const T* xr = x + (size_t)n * FDIM;
        float acc[NJ];
#pragma unroll
        for (int j = 0; j < NJ; j++) acc[j] = 0.f;
        for (int k = lane; k < FDIM; k += 32) {
            float xv = (float)xr[k];
#pragma unroll
            for (int j = 0; j < NJ; j++) acc[j] += xv * sP[k * NJ + j];
        }
#pragma unroll
        for (int j = 0; j < NJ; j++) {
            float v = acc[j];
#pragma unroll
            for (int o = 16; o; o >>= 1) v += __shfl_down_sync(0xffffffffu, v, o);
            if (lane == 0) e[(size_t)n * NJ + j] = v;
        }
    }
}

// ---------------- softmax + weighted gather (vectorized, fp16 out) ----------
__device__ __forceinline__ float2 load2(const float* p, int d2) {
    return ((const float2*)p)[d2];
}
__device__ __forceinline__ float2 load2(const __half* p, int d2) {
    return __half22float2(((const __half2*)p)[d2]);
}

template <int H, int NJ, typename T>
__global__ void __launch_bounds__(384) aggregate(
    const T* __restrict__ x, const float* __restrict__ e,
    const void* __restrict__ edge, __half* __restrict__ agg)
{
    int n = blockIdx.x;
    __shared__ int   s_src[5];
    __shared__ float s_alpha[H][5];
    int tid = threadIdx.x;
    if (tid < 5) {
        int sv = n;
        if (tid < 4) {
            sv = g_is64 ? (int)((const long long*)edge)[(size_t)DEG * n + tid]
                        : ((const int*)edge)[DEG * n + tid];
        }
        s_src[tid] = sv;
    }
    __syncthreads();
    if (tid < H) {
        float ed = e[(size_t)n * NJ + H + tid];
        float l[5];
#pragma unroll
        for (int k = 0; k < 5; k++) {
            float v = e[(size_t)s_src[k] * NJ + tid] + ed;
            l[k] = v >= 0.f ? v : 0.2f * v;
        }
        float m = l[0];
#pragma unroll
        for (int k = 1; k < 5; k++) m = fmaxf(m, l[k]);
        float s = 0.f;
#pragma unroll
        for (int k = 0; k < 5; k++) { l[k] = expf(l[k] - m); s += l[k]; }
        float inv = 1.f / (s + 1e-16f);
#pragma unroll
        for (int k = 0; k < 5; k++) s_alpha[tid][k] = l[k] * inv;
    }
    __syncthreads();
    int d2 = tid;  // 384 threads x 2 dims = 768
    float2 xv[5];
#pragma unroll
    for (int k = 0; k < 5; k++) xv[k] = load2(x + (size_t)s_src[k] * FDIM, d2);
#pragma unroll
    for (int h = 0; h < H; h++) {
        float ax = 0.f, ay = 0.f;
#pragma unroll
        for (int k = 0; k < 5; k++) {
            float al = s_alpha[h][k];
            ax += al * xv[k].x;
            ay += al * xv[k].y;
        }
        ((__half2*)(agg + ((size_t)n * H + h) * FDIM))[d2] =
            __floats2half2_rn(ax, ay);
    }
}

// ---------------- fp16 mma.sync persistent GEMM -----------------------------
// CTA 128x128, BK=32, 8 warps (2x4), warp tile 64x32, ldmatrix,
// 4-stage cp.async with cross-tile pipelining.
#define BM 128
#define BN 128
#define BK 32
#define ASTRH 40
#define BSTRH 136
#define A_STG (BM * ASTRH)
#define B_STG (BK * BSTRH)
#define NSTAGE 4
#define GEMM_SMEM (NSTAGE * (A_STG + B_STG) * 2)

__global__ void __launch_bounds__(256, 2) gemm_fp16(
    const __half* __restrict__ A, const __half* __restrict__ B,
    const float* __restrict__ bias, float* __restrict__ C,
    int Nn, int K, int ntiles, int T)
{
    extern __shared__ __half hsm[];
    uint32_t asb = smem_u32(hsm);
    uint32_t bsb = asb + NSTAGE * A_STG * 2;

    int tid = threadIdx.x;
    int lane = tid & 31, wid = tid >> 5;
    int warpM = wid & 1, warpN = wid >> 1;
    int g = lane >> 2, tg = lane & 3;
    int KT = K / BK;

    // cp.async source coordinates (per thread)
    int ar = tid >> 2, ac8 = (tid & 3) * 8;
    int br = tid >> 4, bc8 = (tid & 15) * 8;

    auto load_stage = [&](int s, int k0, int bm, int bn) {
#pragma unroll
        for (int t = 0; t < 2; t++) {
            int r = ar + t * 64;
            cp16(asb + (uint32_t)(s * A_STG + r * ASTRH + ac8) * 2,
                 A + (size_t)(bm + r) * K + k0 + ac8);
        }
#pragma unroll
        for (int t = 0; t < 2; t++) {
            int r = br + t * 16;
            cp16(bsb + (uint32_t)(s * B_STG + r * BSTRH + bc8) * 2,
                 B + (size_t)(k0 + r) * Nn + bn + bc8);
        }
        asm volatile("cp.async.commit_group;");
    };

    uint32_t a_off = (uint32_t)((warpM * 64 + (lane & 15)) * ASTRH + (lane >> 4) * 8);
    uint32_t b_off = (uint32_t)((lane & 15) * BSTRH + warpN * 32 + (lane >> 4) * 8);

    int t0 = blockIdx.x;
    if (t0 >= T) return;
    {
        int bm = (t0 / ntiles) * BM, bn = (t0 % ntiles) * BN;
        load_stage(0, 0, bm, bn);
        load_stage(1, BK, bm, bn);
        load_stage(2, 2 * BK, bm, bn);
    }

    for (int t = t0; t < T; t += gridDim.x) {
        int bm = (t / ntiles) * BM, bn = (t % ntiles) * BN;
        int tn = t + gridDim.x; if (tn >= T) tn = t;       // dummy reload on last
        int bm2 = (tn / ntiles) * BM, bn2 = (tn % ntiles) * BN;

        float acc[4][4][4];
#pragma unroll
        for (int i = 0; i < 4; i++)
#pragma unroll
            for (int j = 0; j < 4; j++)
#pragma unroll
                for (int r = 0; r < 4; r++) acc[i][j][r] = 0.f;

        for (int kt = 0; kt < KT; kt++) {
            int pf = kt + NSTAGE - 1;
            if (pf < KT) load_stage(pf & 3, pf * BK, bm, bn);
            else         load_stage(pf & 3, (pf - KT) * BK, bm2, bn2);
            asm volatile("cp.async.wait_group 3;");
            __syncthreads();

            int buf = kt & 3;
            uint32_t a_base = asb + (buf * A_STG + a_off) * 2;
            uint32_t b_base = bsb + (buf * B_STG + b_off) * 2;
#pragma unroll
            for (int ks = 0; ks < 2; ks++) {
                uint32_t af[4][4], bf[2][4];
#pragma unroll
                for (int mt = 0; mt < 4; mt++)
                    ldsm_x4(af[mt], a_base + (uint32_t)(mt * 16 * ASTRH + ks * 16) * 2);
#pragma unroll
                for (int np = 0; np < 2; np++)
                    ldsm_x4_t(bf[np], b_base + (uint32_t)(ks * 16 * BSTRH + np * 16) * 2);
#pragma unroll
                for (int mt = 0; mt < 4; mt++)
#pragma unroll
                    for (int np = 0; np < 2; np++) {
                        mma_f16(acc[mt][np * 2 + 0], af[mt], &bf[np][0]);
                        mma_f16(acc[mt][np * 2 + 1], af[mt], &bf[np][2]);
                    }
            }
            __syncthreads();
        }

        // epilogue: bias add + store (registers only; safe vs prefetch)
#pragma unroll
        for (int mt = 0; mt < 4; mt++) {
            int row = bm + warpM * 64 + mt * 16 + g;
#pragma unroll
            for (int nt = 0; nt < 4; nt++) {
                int col = bn + warpN * 32 + nt * 8 + tg * 2;
                float b0 = bias[col], b1 = bias[col + 1];
                float2 v0 = make_float2(acc[mt][nt][0] + b0, acc[mt][nt][1] + b1);
                float2 v1 = make_float2(acc[mt][nt][2] + b0, acc[mt][nt][3] + b1);
                *(float2*)(C + (size_t)row * Nn + col) = v0;
                *(float2*)(C + (size_t)(row + 8) * Nn + col) = v1;
            }
        }
    }
}

// ---------------- elu + layernorm variants ------------------------------------
__global__ void __launch_bounds__(256) elu_ln_h(
    const float* __restrict__ in, const float* __restrict__ gamma,
    const float* __restrict__ beta, __half* __restrict__ out)
{
    __shared__ float red[8];
    __shared__ float s_mu, s_w;
    int n = blockIdx.x;
    int tid = threadIdx.x;
    const float* row = in + (size_t)n * FDIM;
    float y[3];
    float s = 0.f;
#pragma unroll
    for (int i = 0; i < 3; i++) {
        float v = row[tid + i * 256];
        y[i] = v > 0.f ? v : expm1f(v);
        s += y[i];
    }
    float tot = block_reduce_256(s, red);
    if (tid == 0) s_mu = tot * (1.f / FDIM);
    __syncthreads();
    float mu = s_mu;
    float q = 0.f;
#pragma unroll
    for (int i = 0; i < 3; i++) { float d = y[i] - mu; q += d * d; }
    float totq = block_reduce_256(q, red);
    if (tid == 0) s_w = rsqrtf(totq * (1.f / FDIM) + 1e-5f);
    __syncthreads();
    float w = s_w;
#pragma unroll
    for (int i = 0; i < 3; i++) {
        int d = tid + i * 256;
        out[(size_t)n * FDIM + d] = __float2half((y[i] - mu) * w * gamma[d] + beta[d]);
    }
}

__global__ void __launch_bounds__(256) elu_ln_f(
    const float* __restrict__ in, const float* __restrict__ gamma,
    const float* __restrict__ beta, float* __restrict__ out)
{
    __shared__ float red[8];
    __shared__ float s_mu, s_w;
    int n = blockIdx.x;
    int tid = threadIdx.x;
    const float* row = in + (size_t)n * FDIM;
    float y[3];
    float s = 0.f;
#pragma unroll
    for (int i = 0; i < 3; i++) {
        float v = row[tid + i * 256];
        y[i] = v > 0.f ? v : expm1f(v);
        s += y[i];
    }
    float tot = block_reduce_256(s, red);
    if (tid == 0) s_mu = tot * (1.f / FDIM);
    __syncthreads();
    float mu = s_mu;
    float q = 0.f;
#pragma unroll
    for (int i = 0; i < 3; i++) { float d = y[i] - mu; q += d * d; }
    float totq = block_reduce_256(q, red);
    if (tid == 0) s_w = rsqrtf(totq * (1.f / FDIM) + 1e-5f);
    __syncthreads();
    float w = s_w;
#pragma unroll
    for (int i = 0; i < 3; i++) {
        int d = tid + i * 256;
        float o = (y[i] - mu) * w * gamma[d] + beta[d];
        o = fminf(fmaxf(o, -10000.f), 10000.f);
        out[(size_t)n * FDIM + d] = o;
    }
}

// ---------------- launch ------------------------------------------------------
extern "C" void kernel_launch(void* const* d_in, const int* in_sizes, int n_in,
                              void* d_out, int out_size)
{
    const float* x   = (const float*)d_in[0];
    const void*  ei  = d_in[1];
    const float* W1  = (const float*)d_in[2];
    const float* a1s = (const float*)d_in[3];
    const float* a1d = (const float*)d_in[4];
    const float* b1  = (const float*)d_in[5];
    const float* W2  = (const float*)d_in[6];
    const float* a2s = (const float*)d_in[7];
    const float* a2d = (const float*)d_in[8];
    const float* b2  = (const float*)d_in[9];
    const float* gm  = (const float*)d_in[10];
    const float* bt  = (const float*)d_in[11];
    float* out = (float*)d_out;

    float *p1, *p2, *e1, *e2, *pre;
    __half *w1ph, *w2rh, *agg1h, *agg2h, *x1h;
    cudaGetSymbolAddress((void**)&p1,    g_P1);
    cudaGetSymbolAddress((void**)&p2,    g_P2);
    cudaGetSymbolAddress((void**)&w1ph,  g_W1ph);
    cudaGetSymbolAddress((void**)&w2rh,  g_W2rh);
    cudaGetSymbolAddress((void**)&e1,    g_e1);
    cudaGetSymbolAddress((void**)&e2,    g_e2);
    cudaGetSymbolAddress((void**)&agg1h, g_agg1h);
    cudaGetSymbolAddress((void**)&agg2h, g_agg2h);
    cudaGetSymbolAddress((void**)&pre,   g_pre);
    cudaGetSymbolAddress((void**)&x1h,   g_x1h);

    cudaFuncSetAttribute(gemm_fp16, cudaFuncAttributeMaxDynamicSharedMemorySize, GEMM_SMEM);

    const size_t WTOT = (size_t)4 * FDIM * FDIM + (size_t)FDIM * FDIM;

    detect_kernel<<<1, 256>>>((const unsigned long long*)ei);                 // 1
    build_p<<<dim3(FDIM, 10), 256>>>(W1, a1s, a1d, W2, a2s, a2d);             // 2
    build_w<<<(int)((WTOT + 255) / 256), 256>>>(W1, W2);                      // 3

    // layer 1
    compute_e<8, float><<<512, 256>>>(x, p1, e1);                             // 4
    aggregate<4, 8, float><<<NNODES, 384>>>(x, e1, ei, agg1h);                // 5
    gemm_fp16<<<296, 256, GEMM_SMEM>>>(agg1h, w1ph, b1, pre,                  // 6 (ncu)
                                       FDIM, 4 * FDIM, FDIM / BN,
                                       (NNODES / BM) * (FDIM / BN));
    elu_ln_h<<<NNODES, 256>>>(pre, gm, bt, x1h);                              // 7

    // layer 2
    compute_e<2, __half><<<512, 256>>>(x1h, p2, e2);                          // 8
    aggregate<1, 2, __half><<<NNODES, 384>>>(x1h, e2, ei, agg2h);             // 9
    gemm_fp16<<<192, 256, GEMM_SMEM>>>(agg2h, w2rh, b2, pre,                  // 10
                                       FDIM, FDIM, FDIM / BN,
                                       (NNODES / BM) * (FDIM / BN));
    elu_ln_f<<<NNODES, 256>>>(pre, gm, bt, out);                              // 11
}

// round 6
// speedup vs baseline: 1.1036x; 1.1036x over previous
#include <cuda_runtime.h>
#include <cuda_fp16.h>
#include <cstdint>
#include <cstddef>

#define NNODES 16384
#define FDIM   768
#define DEG    4

// ---------------- scratch (device globals; no allocation allowed) ----------
__device__ float  g_P1[FDIM * 8];
__device__ float  g_P2[FDIM * 2];
__device__ __half g_W1ph[(size_t)4 * FDIM * FDIM];    // [3072,768] B GEMM1 (x0.25, fp16)
__device__ __half g_W2rh[(size_t)FDIM * FDIM];        // [768,768]  B GEMM2 (fp16)
__device__ float  g_e1[(size_t)NNODES * 8];
__device__ float  g_e2[(size_t)NNODES * 2];
__device__ __half g_agg1h[(size_t)NNODES * 4 * FDIM]; // [N,3072] A GEMM1 (fp16)
__device__ __half g_agg2h[(size_t)NNODES * FDIM];     // [N,768]  A GEMM2 (fp16)
__device__ float  g_pre[(size_t)NNODES * FDIM];
__device__ __half g_x1h[(size_t)NNODES * FDIM];       // layer-1 output (fp16)
__device__ int    g_is64;

// ---------------- helpers ---------------------------------------------------
__device__ __forceinline__ uint32_t smem_u32(const void* p) {
    uint32_t a;
    asm("{ .reg .u64 t; cvta.to.shared.u64 t, %1; cvt.u32.u64 %0, t; }" : "=r"(a) : "l"(p));
    return a;
}

__device__ __forceinline__ void cp16(uint32_t s, const void* g) {
    asm volatile("cp.async.cg.shared.global [%0], [%1], 16;" :: "r"(s), "l"(g));
}

__device__ __forceinline__ void ldsm_x4(uint32_t* r, uint32_t addr) {
    asm volatile("ldmatrix.sync.aligned.m8n8.x4.shared.b16 {%0,%1,%2,%3}, [%4];"
                 : "=r"(r[0]), "=r"(r[1]), "=r"(r[2]), "=r"(r[3]) : "r"(addr));
}

__device__ __forceinline__ void ldsm_x4_t(uint32_t* r, uint32_t addr) {
    asm volatile("ldmatrix.sync.aligned.m8n8.x4.trans.shared.b16 {%0,%1,%2,%3}, [%4];"
                 : "=r"(r[0]), "=r"(r[1]), "=r"(r[2]), "=r"(r[3]) : "r"(addr));
}

__device__ __forceinline__ void mma_f16(float* d, const uint32_t* a, const uint32_t* b) {
    asm volatile(
        "mma.sync.aligned.m16n8k16.row.col.f32.f16.f16.f32 "
        "{%0,%1,%2,%3}, {%4,%5,%6,%7}, {%8,%9}, {%0,%1,%2,%3};"
        : "+f"(d[0]), "+f"(d[1]), "+f"(d[2]), "+f"(d[3])
        : "r"(a[0]), "r"(a[1]), "r"(a[2]), "r"(a[3]), "r"(b[0]), "r"(b[1]));
}

__device__ __forceinline__ float block_reduce_256(float v, float* red) {
#pragma unroll
    for (int o = 16; o; o >>= 1) v += __shfl_down_sync(0xffffffffu, v, o);
    if ((threadIdx.x & 31) == 0) red[threadIdx.x >> 5] = v;
    __syncthreads();
    float r = 0.f;
    if (threadIdx.x < 8) r = red[threadIdx.x];
    if (threadIdx.x < 32) {
#pragma unroll
        for (int o = 4; o; o >>= 1) r += __shfl_down_sync(0xffu, r, o);
    }
    return r;
}

// ---------------- edge dtype probe ------------------------------------------
__global__ void detect_kernel(const unsigned long long* __restrict__ p) {
    __shared__ int bad;
    if (threadIdx.x == 0) bad = 0;
    __syncthreads();
    for (int i = threadIdx.x; i < 1024; i += blockDim.x)
        if (p[i] > 0xFFFFFFFFull) bad = 1;
    __syncthreads();
    if (threadIdx.x == 0) g_is64 = bad ? 0 : 1;
}

// ---------------- attention projection vectors P = W_h @ a_h ----------------
__global__ void __launch_bounds__(256) build_p(
    const float* __restrict__ W1, const float* __restrict__ a1s, const float* __restrict__ a1d,
    const float* __restrict__ W2, const float* __restrict__ a2s, const float* __restrict__ a2d)
{
    __shared__ float red[8];
    int k = blockIdx.x, j = blockIdx.y;
    const float *w, *a;
    if (j < 8) {
        int h = j & 3;
        w = W1 + (size_t)k * (4 * FDIM) + h * FDIM;
        a = (j < 4 ? a1s : a1d) + h * FDIM;
    } else {
        w = W2 + (size_t)k * FDIM;
        a = (j == 8) ? a2s : a2d;
    }
    float s = 0.f;
    for (int d = threadIdx.x; d < FDIM; d += 256) s += w[d] * a[d];
    float tot = block_reduce_256(s, red);
    if (threadIdx.x == 0) {
        if (j < 8) g_P1[k * 8 + j] = tot;
        else       g_P2[k * 2 + (j - 8)] = tot;
    }
}

// ---------------- merged W prep: W1 repack (x0.25) + W2 to fp16 --------------
__global__ void __launch_bounds__(256) build_w(const float* __restrict__ W1,
                                               const float* __restrict__ W2)
{
    const size_t S1 = (size_t)4 * FDIM * FDIM;
    const size_t S2 = (size_t)FDIM * FDIM;
    size_t idx = (size_t)blockIdx.x * 256 + threadIdx.x;
    if (idx < S1) {
        int j = (int)(idx % FDIM);
        int r = (int)(idx / FDIM);     // h*768 + k
        int h = r / FDIM, k = r % FDIM;
        g_W1ph[idx] = __float2half(0.25f * W1[(size_t)k * (4 * FDIM) + h * FDIM + j]);
    } else if (idx < S1 + S2) {
        size_t i2 = idx - S1;
        g_W2rh[i2] = __float2half(W2[i2]);
    }
}

// ---------------- e1 = x @ P1 (vectorized float4 / LDS.128) -----------------
__global__ void __launch_bounds__(256) compute_e8(
    const float* __restrict__ x, const float* __restrict__ P, float* __restrict__ e)
{
    __shared__ __align__(16) float sP[8 * FDIM];   // transposed [j][k]
    for (int i = threadIdx.x; i < 8 * FDIM; i += 256) {
        int j = i / FDIM, k = i % FDIM;
        sP[j * FDIM + k] = P[k * 8 + j];
    }
    __syncthreads();
    const float4* sP4 = (const float4*)sP;         // [8][192]
    int warp = threadIdx.x >> 5, lane = threadIdx.x & 31;
    for (int n = blockIdx.x * 8 + warp; n < NNODES; n += gridDim.x * 8) {
        const float4* xr = (const float4*)(x + (size_t)n * FDIM);
        float acc[8];
#pragma unroll
        for (int j = 0; j < 8; j++) acc[j] = 0.f;
#pragma unroll
        for (int it = 0; it < 6; it++) {
            float4 v = xr[lane + it * 32];
#pragma unroll
            for (int j = 0; j < 8; j++) {
                float4 p = sP4[j * 192 + lane + it * 32];
                acc[j] += v.x * p.x + v.y * p.y + v.z * p.z + v.w * p.w;
            }
        }
#pragma unroll
        for (int j = 0; j < 8; j++) {
            float s = acc[j];
#pragma unroll
            for (int o = 16; o; o >>= 1) s += __shfl_down_sync(0xffffffffu, s, o);
            if (lane == 0) e[(size_t)n * 8 + j] = s;
        }
    }
}

// ---------------- softmax + weighted gather (vectorized, fp16 out) ----------
__device__ __forceinline__ float2 load2(const float* p, int d2) {
    return ((const float2*)p)[d2];
}
__device__ __forceinline__ float2 load2(const __half* p, int d2) {
    return __half22float2(((const __half2*)p)[d2]);
}

template <int H, int NJ, typename T>
__global__ void __launch_bounds__(384) aggregate(
    const T* __restrict__ x, const float* __restrict__ e,
    const void* __restrict__ edge, __half* __restrict__ agg)
{
    int n = blockIdx.x;
    __shared__ int   s_src[5];
    __shared__ float s_alpha[H][5];
    int tid = threadIdx.x;
    if (tid < 5) {
        int sv = n;
        if (tid < 4) {
            sv = g_is64 ? (int)((const long long*)edge)[(size_t)DEG * n + tid]
                        : ((const int*)edge)[DEG * n + tid];
        }
        s_src[tid] = sv;
    }
    __syncthreads();
    if (tid < H) {
        float ed = e[(size_t)n * NJ + H + tid];
        float l[5];
#pragma unroll
        for (int k = 0; k < 5; k++) {
            float v = e[(size_t)s_src[k] * NJ + tid] + ed;
            l[k] = v >= 0.f ? v : 0.2f * v;
        }
        float m = l[0];
#pragma unroll
        for (int k = 1; k < 5; k++) m = fmaxf(m, l[k]);
        float s = 0.f;
#pragma unroll
        for (int k = 0; k < 5; k++) { l[k] = expf(l[k] - m); s += l[k]; }
        float inv = 1.f / (s + 1e-16f);
#pragma unroll
        for (int k = 0; k < 5; k++) s_alpha[tid][k] = l[k] * inv;
    }
    __syncthreads();
    int d2 = tid;  // 384 threads x 2 dims = 768
    float2 xv[5];
#pragma unroll
    for (int k = 0; k < 5; k++) xv[k] = load2(x + (size_t)s_src[k] * FDIM, d2);
#pragma unroll
    for (int h = 0; h < H; h++) {
        float ax = 0.f, ay = 0.f;
#pragma unroll
        for (int k = 0; k < 5; k++) {
            float al = s_alpha[h][k];
            ax += al * xv[k].x;
            ay += al * xv[k].y;
        }
        ((__half2*)(agg + ((size_t)n * H + h) * FDIM))[d2] =
            __floats2half2_rn(ax, ay);
    }
}

// ---------------- fp16 mma.sync persistent GEMM (1 sync / k-iter) -----------
#define BM 128
#define BN 128
#define BK 32
#define ASTRH 40
#define BSTRH 136
#define A_STG (BM * ASTRH)
#define B_STG (BK * BSTRH)
#define NSTAGE 4
#define GEMM_SMEM (NSTAGE * (A_STG + B_STG) * 2)

__global__ void __launch_bounds__(256, 2) gemm_fp16(
    const __half* __restrict__ A, const __half* __restrict__ B,
    const float* __restrict__ bias, float* __restrict__ C,
    int Nn, int K, int ntiles, int T)
{
    extern __shared__ __half hsm[];
    uint32_t asb = smem_u32(hsm);
    uint32_t bsb = asb + NSTAGE * A_STG * 2;

    int tid = threadIdx.x;
    int lane = tid & 31, wid = tid >> 5;
    int warpM = wid & 1, warpN = wid >> 1;
    int g = lane >> 2, tg = lane & 3;
    int KT = K / BK;

    int ar = tid >> 2, ac8 = (tid & 3) * 8;
    int br = tid >> 4, bc8 = (tid & 15) * 8;

    auto load_stage = [&](int s, int k0, int bm, int bn) {
#pragma unroll
        for (int t = 0; t < 2; t++) {
            int r = ar + t * 64;
            cp16(asb + (uint32_t)(s * A_STG + r * ASTRH + ac8) * 2,
                 A + (size_t)(bm + r) * K + k0 + ac8);
        }
#pragma unroll
        for (int t = 0; t < 2; t++) {
            int r = br + t * 16;
            cp16(bsb + (uint32_t)(s * B_STG + r * BSTRH + bc8) * 2,
                 B + (size_t)(k0 + r) * Nn + bn + bc8);
        }
        asm volatile("cp.async.commit_group;");
    };

    uint32_t a_off = (uint32_t)((warpM * 64 + (lane & 15)) * ASTRH + (lane >> 4) * 8);
    uint32_t b_off = (uint32_t)((lane & 15) * BSTRH + warpN * 32 + (lane >> 4) * 8);

    int t0 = blockIdx.x;
    if (t0 >= T) return;
    {
        int bm = (t0 / ntiles) * BM, bn = (t0 % ntiles) * BN;
        load_stage(0, 0, bm, bn);
        load_stage(1, BK, bm, bn);
        load_stage(2, 2 * BK, bm, bn);
    }

    for (int t = t0; t < T; t += gridDim.x) {
        int bm = (t / ntiles) * BM, bn = (t % ntiles) * BN;
        int tn = t + gridDim.x; if (tn >= T) tn = t;       // dummy reload on last
        int bm2 = (tn / ntiles) * BM, bn2 = (tn % ntiles) * BN;

        float acc[4][4][4];
#pragma unroll
        for (int i = 0; i < 4; i++)
#pragma unroll
            for (int j = 0; j < 4; j++)
#pragma unroll
                for (int r = 0; r < 4; r++) acc[i][j][r] = 0.f;

        for (int kt = 0; kt < KT; kt++) {
            // stage kt's data needed now: own groups outstanding <= 2
            asm volatile("cp.async.wait_group 2;");
            __syncthreads();   // publishes stage kt; retires reads of buf (kt-1)&3

            // prefetch stage kt+3 (buffer (kt-1)&3 — safe after the sync above)
            int pf = kt + NSTAGE - 1;
            if (pf < KT) load_stage(pf & 3, pf * BK, bm, bn);
            else         load_stage(pf & 3, (pf - KT) * BK, bm2, bn2);

            int buf = kt & 3;
            uint32_t a_base = asb + (buf * A_STG + a_off) * 2;
            uint32_t b_base = bsb + (buf * B_STG + b_off) * 2;
#pragma unroll
            for (int ks = 0; ks < 2; ks++) {
                uint32_t af[4][4], bf[2][4];
#pragma unroll
                for (int mt = 0; mt < 4; mt++)
                    ldsm_x4(af[mt], a_base + (uint32_t)(mt * 16 * ASTRH + ks * 16) * 2);
#pragma unroll
                for (int np = 0; np < 2; np++)
                    ldsm_x4_t(bf[np], b_base + (uint32_t)(ks * 16 * BSTRH + np * 16) * 2);
#pragma unroll
                for (int mt = 0; mt < 4; mt++)
#pragma unroll
                    for (int np = 0; np < 2; np++) {
                        mma_f16(acc[mt][np * 2 + 0], af[mt], &bf[np][0]);
                        mma_f16(acc[mt][np * 2 + 1], af[mt], &bf[np][2]);
                    }
            }
        }

        // epilogue: bias add + store (registers only; no smem touched)
#pragma unroll
        for (int mt = 0; mt < 4; mt++) {
            int row = bm + warpM * 64 + mt * 16 + g;
#pragma unroll
            for (int nt = 0; nt < 4; nt++) {
                int col = bn + warpN * 32 + nt * 8 + tg * 2;
                float b0 = bias[col], b1 = bias[col + 1];
                float2 v0 = make_float2(acc[mt][nt][0] + b0, acc[mt][nt][1] + b1);
                float2 v1 = make_float2(acc[mt][nt][2] + b0, acc[mt][nt][3] + b1);
                *(float2*)(C + (size_t)row * Nn + col) = v0;
                *(float2*)(C + (size_t)(row + 8) * Nn + col) = v1;
            }
        }
    }
    asm volatile("cp.async.wait_group 0;");   // drain before exit
}

// ---------------- elu + LN + fused e2 logits (layer-1 epilogue) --------------
__global__ void __launch_bounds__(256) elu_ln_e2(
    const float* __restrict__ in, const float* __restrict__ gamma,
    const float* __restrict__ beta, const float* __restrict__ P2,
    __half* __restrict__ out, float* __restrict__ e2)
{
    __shared__ float red[8];
    __shared__ float s_mu, s_w;
    int n = blockIdx.x;
    int tid = threadIdx.x;
    const float* row = in + (size_t)n * FDIM;
    float y[3];
    float s = 0.f;
#pragma unroll
    for (int i = 0; i < 3; i++) {
        float v = row[tid + i * 256];
        y[i] = v > 0.f ? v : expm1f(v);
        s += y[i];
    }
    float tot = block_reduce_256(s, red);
    if (tid == 0) s_mu = tot * (1.f / FDIM);
    __syncthreads();
    float mu = s_mu;
    float q = 0.f;
#pragma unroll
    for (int i = 0; i < 3; i++) { float d = y[i] - mu; q += d * d; }
    float totq = block_reduce_256(q, red);
    if (tid == 0) s_w = rsqrtf(totq * (1.f / FDIM) + 1e-5f);
    __syncthreads();
    float w = s_w;
    float o3[3];
#pragma unroll
    for (int i = 0; i < 3; i++) {
        int d = tid + i * 256;
        o3[i] = (y[i] - mu) * w * gamma[d] + beta[d];
        out[(size_t)n * FDIM + d] = __float2half(o3[i]);
    }
    // fused e2 = x1 . P2  (two block reductions)
    float s0 = 0.f, s1 = 0.f;
#pragma unroll
    for (int i = 0; i < 3; i++) {
        int d = tid + i * 256;
        s0 += o3[i] * P2[d * 2 + 0];
        s1 += o3[i] * P2[d * 2 + 1];
    }
    __syncthreads();
    float t0 = block_reduce_256(s0, red);
    if (tid == 0) e2[(size_t)n * 2 + 0] = t0;
    __syncthreads();
    float t1 = block_reduce_256(s1, red);
    if (tid == 0) e2[(size_t)n * 2 + 1] = t1;
}

// ---------------- final elu + LN + clip (fp32 out) ----------------------------
__global__ void __launch_bounds__(256) elu_ln_f(
    const float* __restrict__ in, const float* __restrict__ gamma,
    const float* __restrict__ beta, float* __restrict__ out)
{
    __shared__ float red[8];
    __shared__ float s_mu, s_w;
    int n = blockIdx.x;
    int tid = threadIdx.x;
    const float* row = in + (size_t)n * FDIM;
    float y[3];
    float s = 0.f;
#pragma unroll
    for (int i = 0; i < 3; i++) {
        float v = row[tid + i * 256];
        y[i] = v > 0.f ? v : expm1f(v);
        s += y[i];
    }
    float tot = block_reduce_256(s, red);
    if (tid == 0) s_mu = tot * (1.f / FDIM);
    __syncthreads();
    float mu = s_mu;
    float q = 0.f;
#pragma unroll
    for (int i = 0; i < 3; i++) { float d = y[i] - mu; q += d * d; }
    float totq = block_reduce_256(q, red);
    if (tid == 0) s_w = rsqrtf(totq * (1.f / FDIM) + 1e-5f);
    __syncthreads();
    float w = s_w;
#pragma unroll
    for (int i = 0; i < 3; i++) {
        int d = tid + i * 256;
        float o = (y[i] - mu) * w * gamma[d] + beta[d];
        o = fminf(fmaxf(o, -10000.f), 10000.f);
        out[(size_t)n * FDIM + d] = o;
    }
}

// ---------------- launch ------------------------------------------------------
extern "C" void kernel_launch(void* const* d_in, const int* in_sizes, int n_in,
                              void* d_out, int out_size)
{
    const float* x   = (const float*)d_in[0];
    const void*  ei  = d_in[1];
    const float* W1  = (const float*)d_in[2];
    const float* a1s = (const float*)d_in[3];
    const float* a1d = (const float*)d_in[4];
    const float* b1  = (const float*)d_in[5];
    const float* W2  = (const float*)d_in[6];
    const float* a2s = (const float*)d_in[7];
    const float* a2d = (const float*)d_in[8];
    const float* b2  = (const float*)d_in[9];
    const float* gm  = (const float*)d_in[10];
    const float* bt  = (const float*)d_in[11];
    float* out = (float*)d_out;

    float *p1, *p2, *e1, *e2, *pre;
    __half *w1ph, *w2rh, *agg1h, *agg2h, *x1h;
    cudaGetSymbolAddress((void**)&p1,    g_P1);
    cudaGetSymbolAddress((void**)&p2,    g_P2);
    cudaGetSymbolAddress((void**)&w1ph,  g_W1ph);
    cudaGetSymbolAddress((void**)&w2rh,  g_W2rh);
    cudaGetSymbolAddress((void**)&e1,    g_e1);
    cudaGetSymbolAddress((void**)&e2,    g_e2);
    cudaGetSymbolAddress((void**)&agg1h, g_agg1h);
    cudaGetSymbolAddress((void**)&agg2h, g_agg2h);
    cudaGetSymbolAddress((void**)&pre,   g_pre);
    cudaGetSymbolAddress((void**)&x1h,   g_x1h);

    cudaFuncSetAttribute(gemm_fp16, cudaFuncAttributeMaxDynamicSharedMemorySize, GEMM_SMEM);

    const size_t WTOT = (size_t)4 * FDIM * FDIM + (size_t)FDIM * FDIM;
    const int T = (NNODES / BM) * (FDIM / BN);   // 768 tiles

    detect_kernel<<<1, 256>>>((const unsigned long long*)ei);                 // 1
    build_p<<<dim3(FDIM, 10), 256>>>(W1, a1s, a1d, W2, a2s, a2d);             // 2
    build_w<<<(int)((WTOT + 255) / 256), 256>>>(W1, W2);                      // 3

    // layer 1
    compute_e8<<<512, 256>>>(x, p1, e1);                                      // 4
    aggregate<4, 8, float><<<NNODES, 384>>>(x, e1, ei, agg1h);                // 5
    gemm_fp16<<<296, 256, GEMM_SMEM>>>(agg1h, w1ph, b1, pre,                  // 6 (ncu)
                                       FDIM, 4 * FDIM, FDIM / BN, T);
    elu_ln_e2<<<NNODES, 256>>>(pre, gm, bt, p2, x1h, e2);                     // 7

    // layer 2
    aggregate<1, 2, __half><<<NNODES, 384>>>(x1h, e2, ei, agg2h);             // 8
    gemm_fp16<<<296, 256, GEMM_SMEM>>>(agg2h, w2rh, b2, pre,                  // 9
                                       FDIM, FDIM, FDIM / BN, T);
    elu_ln_f<<<NNODES, 256>>>(pre, gm, bt, out);                              // 10
}

// round 7
// speedup vs baseline: 1.1038x; 1.0002x over previous
#include <cuda_runtime.h>
#include <cuda_fp16.h>
#include <cstdint>
#include <cstddef>

#define NNODES 16384
#define FDIM   768
#define DEG    4

// ---------------- scratch (device globals; no allocation allowed) ----------
__device__ float  g_P1[FDIM * 8];
__device__ float  g_P2[FDIM * 2];
__device__ __half g_W1ph[(size_t)4 * FDIM * FDIM];    // [3072,768] B GEMM1 (x0.25, fp16)
__device__ __half g_W2rh[(size_t)FDIM * FDIM];        // [768,768]  B GEMM2 (fp16)
__device__ float  g_e1[(size_t)NNODES * 8];
__device__ float  g_e2[(size_t)NNODES * 2];
__device__ __half g_agg1h[(size_t)NNODES * 4 * FDIM]; // [N,3072] A GEMM1 (fp16)
__device__ __half g_agg2h[(size_t)NNODES * FDIM];     // [N,768]  A GEMM2 (fp16)
__device__ __half g_preh[(size_t)NNODES * FDIM];      // GEMM output (fp16)
__device__ __half g_x1h[(size_t)NNODES * FDIM];       // layer-1 output (fp16)
__device__ int    g_is64;

// ---------------- helpers ---------------------------------------------------
__device__ __forceinline__ uint32_t smem_u32(const void* p) {
    uint32_t a;
    asm("{ .reg .u64 t; cvta.to.shared.u64 t, %1; cvt.u32.u64 %0, t; }" : "=r"(a) : "l"(p));
    return a;
}

__device__ __forceinline__ void cp16(uint32_t s, const void* g) {
    asm volatile("cp.async.cg.shared.global [%0], [%1], 16;" :: "r"(s), "l"(g));
}

__device__ __forceinline__ void ldsm_x4(uint32_t* r, uint32_t addr) {
    asm volatile("ldmatrix.sync.aligned.m8n8.x4.shared.b16 {%0,%1,%2,%3}, [%4];"
                 : "=r"(r[0]), "=r"(r[1]), "=r"(r[2]), "=r"(r[3]) : "r"(addr));
}

__device__ __forceinline__ void ldsm_x4_t(uint32_t* r, uint32_t addr) {
    asm volatile("ldmatrix.sync.aligned.m8n8.x4.trans.shared.b16 {%0,%1,%2,%3}, [%4];"
                 : "=r"(r[0]), "=r"(r[1]), "=r"(r[2]), "=r"(r[3]) : "r"(addr));
}

__device__ __forceinline__ void mma_f16(float* d, const uint32_t* a, const uint32_t* b) {
    asm volatile(
        "mma.sync.aligned.m16n8k16.row.col.f32.f16.f16.f32 "
        "{%0,%1,%2,%3}, {%4,%5,%6,%7}, {%8,%9}, {%0,%1,%2,%3};"
        : "+f"(d[0]), "+f"(d[1]), "+f"(d[2]), "+f"(d[3])
        : "r"(a[0]), "r"(a[1]), "r"(a[2]), "r"(a[3]), "r"(b[0]), "r"(b[1]));
}

__device__ __forceinline__ float block_reduce_256(float v, float* red) {
#pragma unroll
    for (int o = 16; o; o >>= 1) v += __shfl_down_sync(0xffffffffu, v, o);
    if ((threadIdx.x & 31) == 0) red[threadIdx.x >> 5] = v;
    __syncthreads();
    float r = 0.f;
    if (threadIdx.x < 8) r = red[threadIdx.x];
    if (threadIdx.x < 32) {
#pragma unroll
        for (int o = 4; o; o >>= 1) r += __shfl_down_sync(0xffu, r, o);
    }
    return r;
}

// ---------------- merged prep: detect + build_p + build_w --------------------
// block 0: edge dtype probe
// blocks [1, 7681): P vectors (k = idx%768, j = idx/768, j<10)
// blocks [7681, 19201): W repack/convert
#define PREP_PBLK (FDIM * 10)
#define PREP_WELEM ((size_t)5 * FDIM * FDIM)
#define PREP_WBLK ((int)((PREP_WELEM + 255) / 256))
#define PREP_GRID (1 + PREP_PBLK + PREP_WBLK)

__global__ void __launch_bounds__(256) prep(
    const float* __restrict__ W1, const float* __restrict__ a1s, const float* __restrict__ a1d,
    const float* __restrict__ W2, const float* __restrict__ a2s, const float* __restrict__ a2d,
    const unsigned long long* __restrict__ edge)
{
    int b = blockIdx.x;
    if (b == 0) {
        __shared__ int bad;
        if (threadIdx.x == 0) bad = 0;
        __syncthreads();
        for (int i = threadIdx.x; i < 1024; i += 256)
            if (edge[i] > 0xFFFFFFFFull) bad = 1;
        __syncthreads();
        if (threadIdx.x == 0) g_is64 = bad ? 0 : 1;
        return;
    }
    if (b < 1 + PREP_PBLK) {
        __shared__ float red[8];
        int idx = b - 1;
        int k = idx % FDIM, j = idx / FDIM;
        const float *w, *a;
        if (j < 8) {
            int h = j & 3;
            w = W1 + (size_t)k * (4 * FDIM) + h * FDIM;
            a = (j < 4 ? a1s : a1d) + h * FDIM;
        } else {
            w = W2 + (size_t)k * FDIM;
            a = (j == 8) ? a2s : a2d;
        }
        float s = 0.f;
        for (int d = threadIdx.x; d < FDIM; d += 256) s += w[d] * a[d];
        float tot = block_reduce_256(s, red);
        if (threadIdx.x == 0) {
            if (j < 8) g_P1[k * 8 + j] = tot;
            else       g_P2[k * 2 + (j - 8)] = tot;
        }
        return;
    }
    const size_t S1 = (size_t)4 * FDIM * FDIM;
    size_t idx = (size_t)(b - 1 - PREP_PBLK) * 256 + threadIdx.x;
    if (idx < S1) {
        int j = (int)(idx % FDIM);
        int r = (int)(idx / FDIM);     // h*768 + k
        int h = r / FDIM, k = r % FDIM;
        g_W1ph[idx] = __float2half(0.25f * W1[(size_t)k * (4 * FDIM) + h * FDIM + j]);
    } else if (idx < PREP_WELEM) {
        size_t i2 = idx - S1;
        g_W2rh[i2] = __float2half(W2[i2]);
    }
}

// ---------------- e1 = x @ P1 (1 node/warp, float4/LDS.128) -----------------
__global__ void __launch_bounds__(256, 3) compute_e8(
    const float* __restrict__ x, const float* __restrict__ P, float* __restrict__ e)
{
    __shared__ __align__(16) float sP[8 * FDIM];   // transposed [j][k]
    for (int i = threadIdx.x; i < 8 * FDIM; i += 256) {
        int j = i / FDIM, k = i % FDIM;
        sP[j * FDIM + k] = P[k * 8 + j];
    }
    __syncthreads();
    const float4* sP4 = (const float4*)sP;         // [8][192]
    int warp = threadIdx.x >> 5, lane = threadIdx.x & 31;
    int n = blockIdx.x * 8 + warp;                 // grid = 2048 -> exactly 1 node/warp
    const float4* xr = (const float4*)(x + (size_t)n * FDIM);
    float acc[8];
#pragma unroll
    for (int j = 0; j < 8; j++) acc[j] = 0.f;
#pragma unroll
    for (int it = 0; it < 6; it++) {
        float4 v = xr[lane + it * 32];
#pragma unroll
        for (int j = 0; j < 8; j++) {
            float4 p = sP4[j * 192 + lane + it * 32];
            acc[j] += v.x * p.x + v.y * p.y + v.z * p.z + v.w * p.w;
        }
    }
#pragma unroll
    for (int j = 0; j < 8; j++) {
        float s = acc[j];
#pragma unroll
        for (int o = 16; o; o >>= 1) s += __shfl_down_sync(0xffffffffu, s, o);
        if (lane == 0) e[(size_t)n * 8 + j] = s;
    }
}

// ---------------- softmax + weighted gather (vectorized, fp16 out) ----------
__device__ __forceinline__ float2 load2(const float* p, int d2) {
    return ((const float2*)p)[d2];
}
__device__ __forceinline__ float2 load2(const __half* p, int d2) {
    return __half22float2(((const __half2*)p)[d2]);
}

template <int H, int NJ, typename T>
__global__ void __launch_bounds__(384) aggregate(
    const T* __restrict__ x, const float* __restrict__ e,
    const void* __restrict__ edge, __half* __restrict__ agg)
{
    int n = blockIdx.x;
    __shared__ int   s_src[5];
    __shared__ float s_alpha[H][5];
    int tid = threadIdx.x;
    if (tid < 5) {
        int sv = n;
        if (tid < 4) {
            sv = g_is64 ? (int)((const long long*)edge)[(size_t)DEG * n + tid]
                        : ((const int*)edge)[DEG * n + tid];
        }
        s_src[tid] = sv;
    }
    __syncthreads();
    if (tid < H) {
        float ed = e[(size_t)n * NJ + H + tid];
        float l[5];
#pragma unroll
        for (int k = 0; k < 5; k++) {
            float v = e[(size_t)s_src[k] * NJ + tid] + ed;
            l[k] = v >= 0.f ? v : 0.2f * v;
        }
        float m = l[0];
#pragma unroll
        for (int k = 1; k < 5; k++) m = fmaxf(m, l[k]);
        float s = 0.f;
#pragma unroll
        for (int k = 0; k < 5; k++) { l[k] = expf(l[k] - m); s += l[k]; }
        float inv = 1.f / (s + 1e-16f);
#pragma unroll
        for (int k = 0; k < 5; k++) s_alpha[tid][k] = l[k] * inv;
    }
    __syncthreads();
    int d2 = tid;  // 384 threads x 2 dims = 768
    float2 xv[5];
#pragma unroll
    for (int k = 0; k < 5; k++) xv[k] = load2(x + (size_t)s_src[k] * FDIM, d2);
#pragma unroll
    for (int h = 0; h < H; h++) {
        float ax = 0.f, ay = 0.f;
#pragma unroll
        for (int k = 0; k < 5; k++) {
            float al = s_alpha[h][k];
            ax += al * xv[k].x;
            ay += al * xv[k].y;
        }
        ((__half2*)(agg + ((size_t)n * H + h) * FDIM))[d2] =
            __floats2half2_rn(ax, ay);
    }
}

// ---------------- fp16 mma.sync persistent GEMM (1 sync / k-iter) -----------
#define BM 128
#define BN 128
#define BK 32
#define ASTRH 40
#define BSTRH 136
#define A_STG (BM * ASTRH)
#define B_STG (BK * BSTRH)
#define NSTAGE 4
#define GEMM_SMEM (NSTAGE * (A_STG + B_STG) * 2)

__global__ void __launch_bounds__(256, 2) gemm_fp16(
    const __half* __restrict__ A, const __half* __restrict__ B,
    const float* __restrict__ bias, __half* __restrict__ C,
    int Nn, int K, int ntiles, int T)
{
    extern __shared__ __half hsm[];
    uint32_t asb = smem_u32(hsm);
    uint32_t bsb = asb + NSTAGE * A_STG * 2;

    int tid = threadIdx.x;
    int lane = tid & 31, wid = tid >> 5;
    int warpM = wid & 1, warpN = wid >> 1;
    int g = lane >> 2, tg = lane & 3;
    int KT = K / BK;

    int ar = tid >> 2, ac8 = (tid & 3) * 8;
    int br = tid >> 4, bc8 = (tid & 15) * 8;

    auto load_stage = [&](int s, int k0, int bm, int bn) {
#pragma unroll
        for (int t = 0; t < 2; t++) {
            int r = ar + t * 64;
            cp16(asb + (uint32_t)(s * A_STG + r * ASTRH + ac8) * 2,
                 A + (size_t)(bm + r) * K + k0 + ac8);
        }
#pragma unroll
        for (int t = 0; t < 2; t++) {
            int r = br + t * 16;
            cp16(bsb + (uint32_t)(s * B_STG + r * BSTRH + bc8) * 2,
                 B + (size_t)(k0 + r) * Nn + bn + bc8);
        }
        asm volatile("cp.async.commit_group;");
    };

    uint32_t a_off = (uint32_t)((warpM * 64 + (lane & 15)) * ASTRH + (lane >> 4) * 8);
    uint32_t b_off = (uint32_t)((lane & 15) * BSTRH + warpN * 32 + (lane >> 4) * 8);

    int t0 = blockIdx.x;
    if (t0 >= T) return;
    {
        int bm = (t0 / ntiles) * BM, bn = (t0 % ntiles) * BN;
        load_stage(0, 0, bm, bn);
        load_stage(1, BK, bm, bn);
        load_stage(2, 2 * BK, bm, bn);
    }

    for (int t = t0; t < T; t += gridDim.x) {
        int bm = (t / ntiles) * BM, bn = (t % ntiles) * BN;
        int tn = t + gridDim.x; if (tn >= T) tn = t;       // dummy reload on last
        int bm2 = (tn / ntiles) * BM, bn2 = (tn % ntiles) * BN;

        float acc[4][4][4];
#pragma unroll
        for (int i = 0; i < 4; i++)
#pragma unroll
            for (int j = 0; j < 4; j++)
#pragma unroll
                for (int r = 0; r < 4; r++) acc[i][j][r] = 0.f;

        for (int kt = 0; kt < KT; kt++) {
            asm volatile("cp.async.wait_group 2;");
            __syncthreads();   // publishes stage kt; retires reads of buf (kt-1)&3

            int pf = kt + NSTAGE - 1;
            if (pf < KT) load_stage(pf & 3, pf * BK, bm, bn);
            else         load_stage(pf & 3, (pf - KT) * BK, bm2, bn2);

            int buf = kt & 3;
            uint32_t a_base = asb + (buf * A_STG + a_off) * 2;
            uint32_t b_base = bsb + (buf * B_STG + b_off) * 2;
#pragma unroll
            for (int ks = 0; ks < 2; ks++) {
                uint32_t af[4][4], bf[2][4];
#pragma unroll
                for (int mt = 0; mt < 4; mt++)
                    ldsm_x4(af[mt], a_base + (uint32_t)(mt * 16 * ASTRH + ks * 16) * 2);
#pragma unroll
                for (int np = 0; np < 2; np++)
                    ldsm_x4_t(bf[np], b_base + (uint32_t)(ks * 16 * BSTRH + np * 16) * 2);
#pragma unroll
                for (int mt = 0; mt < 4; mt++)
#pragma unroll
                    for (int np = 0; np < 2; np++) {
                        mma_f16(acc[mt][np * 2 + 0], af[mt], &bf[np][0]);
                        mma_f16(acc[mt][np * 2 + 1], af[mt], &bf[np][2]);
                    }
            }
        }

        // epilogue: bias add + half2 store (registers only; no smem touched)
#pragma unroll
        for (int mt = 0; mt < 4; mt++) {
            int row = bm + warpM * 64 + mt * 16 + g;
#pragma unroll
            for (int nt = 0; nt < 4; nt++) {
                int col = bn + warpN * 32 + nt * 8 + tg * 2;
                float b0 = bias[col], b1 = bias[col + 1];
                *(__half2*)(C + (size_t)row * Nn + col) =
                    __floats2half2_rn(acc[mt][nt][0] + b0, acc[mt][nt][1] + b1);
                *(__half2*)(C + (size_t)(row + 8) * Nn + col) =
                    __floats2half2_rn(acc[mt][nt][2] + b0, acc[mt][nt][3] + b1);
            }
        }
    }
    asm volatile("cp.async.wait_group 0;");   // drain before exit
}

// ---------------- elu + LN + fused e2 logits (layer-1 epilogue) --------------
__global__ void __launch_bounds__(256) elu_ln_e2(
    const __half* __restrict__ in, const float* __restrict__ gamma,
    const float* __restrict__ beta, const float* __restrict__ P2,
    __half* __restrict__ out, float* __restrict__ e2)
{
    __shared__ float red[8];
    __shared__ float s_mu, s_w;
    int n = blockIdx.x;
    int tid = threadIdx.x;
    const __half* row = in + (size_t)n * FDIM;
    float y[3];
    float s = 0.f;
#pragma unroll
    for (int i = 0; i < 3; i++) {
        float v = __half2float(row[tid + i * 256]);
        y[i] = v > 0.f ? v : expm1f(v);
        s += y[i];
    }
    float tot = block_reduce_256(s, red);
    if (tid == 0) s_mu = tot * (1.f / FDIM);
    __syncthreads();
    float mu = s_mu;
    float q = 0.f;
#pragma unroll
    for (int i = 0; i < 3; i++) { float d = y[i] - mu; q += d * d; }
    float totq = block_reduce_256(q, red);
    if (tid == 0) s_w = rsqrtf(totq * (1.f / FDIM) + 1e-5f);
    __syncthreads();
    float w = s_w;
    float o3[3];
#pragma unroll
    for (int i = 0; i < 3; i++) {
        int d = tid + i * 256;
        o3[i] = (y[i] - mu) * w * gamma[d] + beta[d];
        out[(size_t)n * FDIM + d] = __float2half(o3[i]);
    }
    float s0 = 0.f, s1 = 0.f;
#pragma unroll
    for (int i = 0; i < 3; i++) {
        int d = tid + i * 256;
        s0 += o3[i] * P2[d * 2 + 0];
        s1 += o3[i] * P2[d * 2 + 1];
    }
    __syncthreads();
    float t0 = block_reduce_256(s0, red);
    if (tid == 0) e2[(size_t)n * 2 + 0] = t0;
    __syncthreads();
    float t1 = block_reduce_256(s1, red);
    if (tid == 0) e2[(size_t)n * 2 + 1] = t1;
}

// ---------------- final elu + LN + clip (fp32 out) ----------------------------
__global__ void __launch_bounds__(256) elu_ln_f(
    const __half* __restrict__ in, const float* __restrict__ gamma,
    const float* __restrict__ beta, float* __restrict__ out)
{
    __shared__ float red[8];
    __shared__ float s_mu, s_w;
    int n = blockIdx.x;
    int tid = threadIdx.x;
    const __half* row = in + (size_t)n * FDIM;
    float y[3];
    float s = 0.f;
#pragma unroll
    for (int i = 0; i < 3; i++) {
        float v = __half2float(row[tid + i * 256]);
        y[i] = v > 0.f ? v : expm1f(v);
        s += y[i];
    }
    float tot = block_reduce_256(s, red);
    if (tid == 0) s_mu = tot * (1.f / FDIM);
    __syncthreads();
    float mu = s_mu;
    float q = 0.f;
#pragma unroll
    for (int i = 0; i < 3; i++) { float d = y[i] - mu; q += d * d; }
    float totq = block_reduce_256(q, red);
    if (tid == 0) s_w = rsqrtf(totq * (1.f / FDIM) + 1e-5f);
    __syncthreads();
    float w = s_w;
#pragma unroll
    for (int i = 0; i < 3; i++) {
        int d = tid + i * 256;
        float o = (y[i] - mu) * w * gamma[d] + beta[d];
        o = fminf(fmaxf(o, -10000.f), 10000.f);
        out[(size_t)n * FDIM + d] = o;
    }
}

// ---------------- launch ------------------------------------------------------
extern "C" void kernel_launch(void* const* d_in, const int* in_sizes, int n_in,
                              void* d_out, int out_size)
{
    const float* x   = (const float*)d_in[0];
    const void*  ei  = d_in[1];
    const float* W1  = (const float*)d_in[2];
    const float* a1s = (const float*)d_in[3];
    const float* a1d = (const float*)d_in[4];
    const float* b1  = (const float*)d_in[5];
    const float* W2  = (const float*)d_in[6];
    const float* a2s = (const float*)d_in[7];
    const float* a2d = (const float*)d_in[8];
    const float* b2  = (const float*)d_in[9];
    const float* gm  = (const float*)d_in[10];
    const float* bt  = (const float*)d_in[11];
    float* out = (float*)d_out;

    float *p1, *p2, *e1, *e2;
    __half *w1ph, *w2rh, *agg1h, *agg2h, *preh, *x1h;
    cudaGetSymbolAddress((void**)&p1,    g_P1);
    cudaGetSymbolAddress((void**)&p2,    g_P2);
    cudaGetSymbolAddress((void**)&w1ph,  g_W1ph);
    cudaGetSymbolAddress((void**)&w2rh,  g_W2rh);
    cudaGetSymbolAddress((void**)&e1,    g_e1);
    cudaGetSymbolAddress((void**)&e2,    g_e2);
    cudaGetSymbolAddress((void**)&agg1h, g_agg1h);
    cudaGetSymbolAddress((void**)&agg2h, g_agg2h);
    cudaGetSymbolAddress((void**)&preh,  g_preh);
    cudaGetSymbolAddress((void**)&x1h,   g_x1h);

    cudaFuncSetAttribute(gemm_fp16, cudaFuncAttributeMaxDynamicSharedMemorySize, GEMM_SMEM);

    const int T = (NNODES / BM) * (FDIM / BN);   // 768 tiles

    prep<<<PREP_GRID, 256>>>(W1, a1s, a1d, W2, a2s, a2d,                      // 1
                             (const unsigned long long*)ei);

    // layer 1
    compute_e8<<<2048, 256>>>(x, p1, e1);                                     // 2
    aggregate<4, 8, float><<<NNODES, 384>>>(x, e1, ei, agg1h);                // 3
    gemm_fp16<<<296, 256, GEMM_SMEM>>>(agg1h, w1ph, b1, preh,                 // 4 (ncu)
                                       FDIM, 4 * FDIM, FDIM / BN, T);
    elu_ln_e2<<<NNODES, 256>>>(preh, gm, bt, p2, x1h, e2);                    // 5

    // layer 2
    aggregate<1, 2, __half><<<NNODES, 384>>>(x1h, e2, ei, agg2h);             // 6
    gemm_fp16<<<296, 256, GEMM_SMEM>>>(agg2h, w2rh, b2, preh,                 // 7
                                       FDIM, FDIM, FDIM / BN, T);
    elu_ln_f<<<NNODES, 256>>>(preh, gm, bt, out);                             // 8
}